// round 15
// baseline (speedup 1.0000x reference)
#include <cuda_runtime.h>
#include <cuda_fp16.h>
#include <cstdint>

#define Bb 4
#define Ss 2048
#define Hh 16
#define Dd 64
#define OUTF 1024

// Scratch as packed half2 words (static device arrays — no runtime allocation).
__device__ uint32_t g_Q[(size_t)Bb * Hh * Ss * Dd / 2];
__device__ uint32_t g_K[(size_t)Bb * Hh * Ss * Dd / 2];
__device__ uint32_t g_V[(size_t)Bb * Hh * Ss * Dd / 2];
__device__ uint32_t g_X[(size_t)Bb * Ss * (Hh * Dd) / 2];
__device__ uint32_t g_Wo[(size_t)OUTF * OUTF / 2];

__device__ __forceinline__ uint32_t h2(float a, float b) {
    __half2 t = __floats2half2_rn(a, b);
    return *(uint32_t*)&t;
}

__device__ __forceinline__ uint32_t ex2h2(uint32_t x) {
    uint32_t y;
    asm("ex2.approx.f16x2 %0, %1;" : "=r"(y) : "r"(x));
    return y;
}

// D += A(16x16 f16 row) * B(16x8 f16 col), fp32 accum.
__device__ __forceinline__ void mma_f16(float* c, const uint32_t* a,
                                        uint32_t b0, uint32_t b1) {
    asm volatile(
        "mma.sync.aligned.m16n8k16.row.col.f32.f16.f16.f32 "
        "{%0,%1,%2,%3}, {%4,%5,%6,%7}, {%8,%9}, {%0,%1,%2,%3};\n"
        : "+f"(c[0]), "+f"(c[1]), "+f"(c[2]), "+f"(c[3])
        : "r"(a[0]), "r"(a[1]), "r"(a[2]), "r"(a[3]), "r"(b0), "r"(b1));
}

// D += A(16x16 f16 row) * B(16x8 f16 col), f16 accum (C = 2 x f16x2 regs).
__device__ __forceinline__ void mma_h16(uint32_t* c, const uint32_t* a,
                                        uint32_t b0, uint32_t b1) {
    asm volatile(
        "mma.sync.aligned.m16n8k16.row.col.f16.f16.f16.f16 "
        "{%0,%1}, {%2,%3,%4,%5}, {%6,%7}, {%0,%1};\n"
        : "+r"(c[0]), "+r"(c[1])
        : "r"(a[0]), "r"(a[1]), "r"(a[2]), "r"(a[3]), "r"(b0), "r"(b1));
}

__device__ __forceinline__ void ldsm4(uint32_t* r, uint32_t addr) {
    asm volatile(
        "ldmatrix.sync.aligned.m8n8.x4.shared.b16 {%0,%1,%2,%3}, [%4];"
        : "=r"(r[0]), "=r"(r[1]), "=r"(r[2]), "=r"(r[3]) : "r"(addr));
}
__device__ __forceinline__ void ldsm4t(uint32_t* r, uint32_t addr) {
    asm volatile(
        "ldmatrix.sync.aligned.m8n8.x4.trans.shared.b16 {%0,%1,%2,%3}, [%4];"
        : "=r"(r[0]), "=r"(r[1]), "=r"(r[2]), "=r"(r[3]) : "r"(addr));
}
__device__ __forceinline__ uint32_t sptr(const void* p) {
    return (uint32_t)__cvta_generic_to_shared(p);
}
__device__ __forceinline__ void cpa16(uint32_t dst, const void* src) {
    asm volatile("cp.async.cg.shared.global [%0], [%1], 16;"
                 :: "r"(dst), "l"(src));
}
__device__ __forceinline__ void cpa_commit() {
    asm volatile("cp.async.commit_group;");
}
__device__ __forceinline__ void cpa_wait0() {
    asm volatile("cp.async.wait_group 0;");
}
__device__ __forceinline__ void cpa_wait1() {
    asm volatile("cp.async.wait_group 1;");
}

extern __shared__ uint32_t dyn_smem[];

// ---------------------------------------------------------------------------
// Kernel 0: Wo fp32 -> fp16 (half2-packed), once per launch.
// ---------------------------------------------------------------------------
__global__ __launch_bounds__(256) void wo2h_kernel(const float* __restrict__ Wo)
{
    int idx = blockIdx.x * 256 + threadIdx.x;
    float2 t = *(const float2*)(Wo + (size_t)idx * 2);
    g_Wo[idx] = h2(t.x, t.y);
}

// ---------------------------------------------------------------------------
// Kernel 1: per-head QKV projections, f16 mma. 8 heads per CTA (R13).
// grid (S/64, B*3, 2), 128 threads.
// ---------------------------------------------------------------------------
__global__ __launch_bounds__(128) void projM_kernel(
    const float* __restrict__ q, const float* __restrict__ k,
    const float* __restrict__ v,
    const float* __restrict__ Wq, const float* __restrict__ Wk,
    const float* __restrict__ Wv)
{
    __shared__ uint32_t xs[64 * 36];
    __shared__ uint32_t ws[2][64 * 36];

    const int tid = threadIdx.x;
    const int warp = tid >> 5, lane = tid & 31;
    const int qr = lane >> 2, qc = lane & 3;
    const int s0 = blockIdx.x * 64;
    const int b  = blockIdx.y & 3;
    const int which = blockIdx.y >> 2;
    const int h0 = blockIdx.z * 8;

    const float* x = (which == 0) ? q : (which == 1) ? k : v;
    const float* W = (which == 0) ? Wq : (which == 1) ? Wk : Wv;
    uint32_t* outb = (which == 0) ? g_Q : (which == 1) ? g_K : g_V;
    const float qs = (which == 0) ? 0.1803368801f : 1.0f;  // 0.125*log2(e)

    for (int i = 0; i < 8; i++) {
        int idx = tid + i * 128;
        int r = idx >> 4, c4 = (idx & 15) << 2;
        float4 t = *(const float4*)(x + ((size_t)(b * Ss + s0 + r)) * Dd + c4);
        *(uint2*)&xs[r * 36 + (c4 >> 1)] = make_uint2(h2(t.x, t.y), h2(t.z, t.w));
        float4 w = *(const float4*)(W + ((size_t)h0 * Dd + r) * Dd + c4);
        *(uint2*)&ws[0][r * 36 + (c4 >> 1)] =
            make_uint2(h2(w.x, w.y), h2(w.z, w.w));
    }
    __syncthreads();

    const int g = lane >> 3, lr = lane & 7;
    const uint32_t afb = sptr(xs) +
        (uint32_t)(((warp * 16 + (g & 1) * 8 + lr) * 36 + (g >> 1) * 4) * 4);
    uint32_t a[4][4];
#pragma unroll
    for (int kt = 0; kt < 4; kt++) ldsm4(a[kt], afb + kt * 32);

    const uint32_t bfb0 = sptr(ws) +
        (uint32_t)((((g >> 1) * 8 + lr) * 36 + (g & 1) * 4) * 4);
    const int rlo = warp * 16 + qr;

    for (int hh = 0; hh < 8; hh++) {
        const int h = h0 + hh;
        float4 wreg[8];
        if (hh + 1 < 8) {
            const float* Wn = W + (size_t)(h + 1) * Dd * Dd;
#pragma unroll
            for (int i = 0; i < 8; i++) {
                int idx = tid + i * 128;
                int r = idx >> 4, c4 = (idx & 15) << 2;
                wreg[i] = *(const float4*)(Wn + (size_t)r * Dd + c4);
            }
        }

        const uint32_t bfb = bfb0 + (uint32_t)(hh & 1) * (64 * 36 * 4);
        float acc[8][4] = {};
#pragma unroll
        for (int kt = 0; kt < 4; kt++) {
#pragma unroll
            for (int p = 0; p < 4; p++) {
                uint32_t bb[4];
                ldsm4(bb, bfb + (uint32_t)(p * 2304 + kt * 32));
                mma_f16(acc[2 * p],     a[kt], bb[0], bb[1]);
                mma_f16(acc[2 * p + 1], a[kt], bb[2], bb[3]);
            }
        }

        uint32_t* o0 = outb + ((size_t)(b * Hh + h)) * Ss * 32
                       + (size_t)(s0 + rlo) * 32;
        uint32_t* o1 = o0 + 8 * 32;
#pragma unroll
        for (int nt = 0; nt < 8; nt++) {
            o0[nt * 4 + qc] = h2(acc[nt][0] * qs, acc[nt][1] * qs);
            o1[nt * 4 + qc] = h2(acc[nt][2] * qs, acc[nt][3] * qs);
        }

        if (hh + 1 < 8) {
#pragma unroll
            for (int i = 0; i < 8; i++) {
                int idx = tid + i * 128;
                int r = idx >> 4, c4 = (idx & 15) << 2;
                *(uint2*)&ws[(hh + 1) & 1][r * 36 + (c4 >> 1)] =
                    make_uint2(h2(wreg[i].x, wreg[i].y),
                               h2(wreg[i].z, wreg[i].w));
            }
        }
        __syncthreads();
    }
}

// ---------------------------------------------------------------------------
// Kernel 2: flash attention. BM=128, BN=64, D=64, 128 threads, 32 Q-rows
// per warp, f16-accum QK^T, 3-stage ring. Softmax denominators computed by
// ONE extra mma per kt with a constant all-ones B fragment (P @ 1): exact
// fp32 row sums in lacc, zero shuffles, zero hadd chains.
// ---------------------------------------------------------------------------
__global__ __launch_bounds__(128, 3) void flash14_kernel()
{
    const uint32_t sbase = sptr(dyn_smem);
    const uint32_t STG = 18432;
    const uint32_t ONES = 0x3C003C00u;   // f16x2 {1.0, 1.0}

    const int tid = threadIdx.x;
    const int warp = tid >> 5, lane = tid & 31;
    const int qr = lane >> 2, qc = lane & 3;
    const int s0 = blockIdx.x * 128;
    const size_t base = ((size_t)(blockIdx.z * Hh + blockIdx.y)) * Ss * 32;
    const uint32_t* Qw = g_Q + base;
    const uint4* Ku4 = (const uint4*)(g_K + base);
    const uint4* Vu4 = (const uint4*)(g_V + base);
    const int rb = warp * 32 + qr;

    const int sr = tid >> 3;
    const int sc = tid & 7;
    uint32_t koff[4];
#pragma unroll
    for (int i = 0; i < 4; i++)
        koff[i] = (uint32_t)(((sr + 16 * i) * 36 + sc * 4) * 4);

#pragma unroll
    for (int t = 0; t < 2; t++) {
        const uint4* Kn = Ku4 + (size_t)t * 512;
        const uint4* Vn = Vu4 + (size_t)t * 512;
        const uint32_t so = sbase + (uint32_t)t * STG;
#pragma unroll
        for (int i = 0; i < 4; i++) {
            cpa16(so + koff[i], Kn + (sr + 16 * i) * 8 + sc);
            cpa16(so + 9216 + koff[i], Vn + (sr + 16 * i) * 8 + sc);
        }
        cpa_commit();
    }

    uint32_t qaL[4][4], qaH[4][4];
    {
        const uint32_t* q0 = Qw + (size_t)(s0 + rb) * 32;
        const uint32_t* q1 = q0 + 8 * 32;
        const uint32_t* q2 = q0 + 16 * 32;
        const uint32_t* q3 = q0 + 24 * 32;
#pragma unroll
        for (int kt = 0; kt < 4; kt++) {
            qaL[kt][0] = q0[8 * kt + qc];
            qaL[kt][1] = q1[8 * kt + qc];
            qaL[kt][2] = q0[8 * kt + qc + 4];
            qaL[kt][3] = q1[8 * kt + qc + 4];
            qaH[kt][0] = q2[8 * kt + qc];
            qaH[kt][1] = q3[8 * kt + qc];
            qaH[kt][2] = q2[8 * kt + qc + 4];
            qaH[kt][3] = q3[8 * kt + qc + 4];
        }
    }

    const int g = lane >> 3, lr = lane & 7;
    const uint32_t kfb = sbase +
        (uint32_t)((((g >> 1) * 8 + lr) * 36 + (g & 1) * 4) * 4);
    const uint32_t vfb = sbase + 9216 +
        (uint32_t)(((((g & 1) * 8) + lr) * 36 + (lane >> 4) * 4) * 4);

    float oaccL[8][4] = {}, oaccH[8][4] = {};
    float laccL[4] = {}, laccH[4] = {};   // P @ ones: fp32 row sums
    int stage = 0;

    for (int jt = 0; jt < Ss / 64; jt++) {
        cpa_wait1();
        __syncthreads();

        if (jt + 2 < Ss / 64) {
            int s2 = stage + 2; if (s2 >= 3) s2 -= 3;
            const uint32_t fo = sbase + (uint32_t)s2 * STG;
            const uint4* Kn = Ku4 + (size_t)(jt + 2) * 512;
            const uint4* Vn = Vu4 + (size_t)(jt + 2) * 512;
#pragma unroll
            for (int i = 0; i < 4; i++) {
                cpa16(fo + koff[i], Kn + (sr + 16 * i) * 8 + sc);
                cpa16(fo + 9216 + koff[i], Vn + (sr + 16 * i) * 8 + sc);
            }
        }
        cpa_commit();

        const uint32_t so = (uint32_t)stage * STG;

        // S = Q K^T, f16 accumulation.
        uint32_t sL[8][2], sH[8][2];
#pragma unroll
        for (int nt = 0; nt < 8; nt++) {
            sL[nt][0] = 0u; sL[nt][1] = 0u;
            sH[nt][0] = 0u; sH[nt][1] = 0u;
        }
#pragma unroll
        for (int kt = 0; kt < 4; kt++) {
#pragma unroll
            for (int p = 0; p < 4; p++) {
                uint32_t kb[4];
                ldsm4(kb, kfb + so + (uint32_t)(p * 2304 + kt * 32));
                mma_h16(sL[2 * p],     qaL[kt], kb[0], kb[1]);
                mma_h16(sL[2 * p + 1], qaL[kt], kb[2], kb[3]);
                mma_h16(sH[2 * p],     qaH[kt], kb[0], kb[1]);
                mma_h16(sH[2 * p + 1], qaH[kt], kb[2], kb[3]);
            }
        }

        // P = exp2(S) directly on f16x2 C-fragments.
        uint32_t peL0[8], peL1[8], peH0[8], peH1[8];
#pragma unroll
        for (int nt = 0; nt < 8; nt++) {
            peL0[nt] = ex2h2(sL[nt][0]);
            peL1[nt] = ex2h2(sL[nt][1]);
            peH0[nt] = ex2h2(sH[nt][0]);
            peH1[nt] = ex2h2(sH[nt][1]);
        }

        // O += P V, and l += P @ ones (denominator on the tensor core).
#pragma unroll
        for (int kt = 0; kt < 4; kt++) {
            uint32_t paL[4] = { peL0[2 * kt], peL1[2 * kt],
                                peL0[2 * kt + 1], peL1[2 * kt + 1] };
            uint32_t paH[4] = { peH0[2 * kt], peH1[2 * kt],
                                peH0[2 * kt + 1], peH1[2 * kt + 1] };
            mma_f16(laccL, paL, ONES, ONES);
            mma_f16(laccH, paH, ONES, ONES);
#pragma unroll
            for (int e0 = 0; e0 < 8; e0 += 2) {
                uint32_t vb[4];
                ldsm4t(vb, vfb + so + (uint32_t)(kt * 2304 + e0 * 16));
                mma_f16(oaccL[e0],     paL, vb[0], vb[1]);
                mma_f16(oaccL[e0 + 1], paL, vb[2], vb[3]);
                mma_f16(oaccH[e0],     paH, vb[0], vb[1]);
                mma_f16(oaccH[e0 + 1], paH, vb[2], vb[3]);
            }
        }

        if (++stage == 3) stage = 0;
    }

    // Denominators: laccX[0] = rowsum(row), laccX[2] = rowsum(row+8).
    float inv0 = 1.0f / laccL[0], inv1 = 1.0f / laccL[2];
    float inv2 = 1.0f / laccH[0], inv3 = 1.0f / laccH[2];
    uint32_t* x0 = g_X + (size_t)(blockIdx.z * Ss + s0 + rb) * 512
                   + blockIdx.y * 32;
    uint32_t* x1 = x0 + (size_t)8 * 512;
    uint32_t* x2 = x0 + (size_t)16 * 512;
    uint32_t* x3 = x0 + (size_t)24 * 512;
#pragma unroll
    for (int et = 0; et < 8; et++) {
        x0[et * 4 + qc] = h2(oaccL[et][0] * inv0, oaccL[et][1] * inv0);
        x1[et * 4 + qc] = h2(oaccL[et][2] * inv1, oaccL[et][3] * inv1);
        x2[et * 4 + qc] = h2(oaccH[et][0] * inv2, oaccH[et][1] * inv2);
        x3[et * 4 + qc] = h2(oaccH[et][2] * inv3, oaccH[et][3] * inv3);
    }
}

// ---------------------------------------------------------------------------
// Kernel 3: output projection (R10 version, unchanged).
// ---------------------------------------------------------------------------
__global__ __launch_bounds__(256, 2) void outproj10_kernel(float* __restrict__ outp)
{
    const uint32_t sbase = sptr(dyn_smem);
    const uint32_t STG = 36864;

    const int tid = threadIdx.x;
    const int warp = tid >> 5, lane = tid & 31;
    const int qr = lane >> 2, qc = lane & 3;
    const int mw = warp >> 1;
    const int nw = warp & 1;
    const int n0 = blockIdx.x * 128;
    const size_t m0 = (size_t)blockIdx.y * 128;
    const int rb = mw * 32 + qr;

    const uint4* Xu4 = (const uint4*)g_X;
    const uint4* Wu4 = (const uint4*)g_Wo;

    const int cr = tid >> 3;
    const int cc = tid & 7;
    uint32_t roff[4];
#pragma unroll
    for (int i = 0; i < 4; i++)
        roff[i] = (uint32_t)(((cr + 32 * i) * 36 + cc * 4) * 4);

#pragma unroll
    for (int i = 0; i < 4; i++) {
        int r = cr + 32 * i;
        cpa16(sbase + roff[i], Xu4 + (m0 + r) * 128 + cc);
        cpa16(sbase + 18432 + roff[i], Wu4 + (size_t)(n0 + r) * 128 + cc);
    }
    cpa_commit();

    const int g = lane >> 3, lr = lane & 7;
    const uint32_t afbL = sbase +
        (uint32_t)(((mw * 32 + (g & 1) * 8 + lr) * 36 + (g >> 1) * 4) * 4);
    const uint32_t afbH = afbL + 16 * 36 * 4;
    const uint32_t bfb = sbase + 18432 +
        (uint32_t)(((nw * 64 + (g >> 1) * 8 + lr) * 36 + (g & 1) * 4) * 4);

    float accL[8][4] = {}, accH[8][4] = {};

    for (int kc = 0; kc < 16; kc++) {
        cpa_wait0();
        __syncthreads();

        if (kc + 1 < 16) {
            const uint32_t fo = sbase + (uint32_t)((kc + 1) & 1) * STG;
            const int k4 = (kc + 1) * 8;
#pragma unroll
            for (int i = 0; i < 4; i++) {
                int r = cr + 32 * i;
                cpa16(fo + roff[i], Xu4 + (m0 + r) * 128 + k4 + cc);
                cpa16(fo + 18432 + roff[i],
                      Wu4 + (size_t)(n0 + r) * 128 + k4 + cc);
            }
            cpa_commit();
        }

        const uint32_t so = (uint32_t)(kc & 1) * STG;
#pragma unroll
        for (int kt = 0; kt < 4; kt++) {
            uint32_t aL[4], aH[4];
            ldsm4(aL, afbL + so + (uint32_t)(kt * 32));
            ldsm4(aH, afbH + so + (uint32_t)(kt * 32));
#pragma unroll
            for (int p = 0; p < 4; p++) {
                uint32_t bb[4];
                ldsm4(bb, bfb + so + (uint32_t)(p * 2304 + kt * 32));
                mma_f16(accL[2 * p],     aL, bb[0], bb[1]);
                mma_f16(accL[2 * p + 1], aL, bb[2], bb[3]);
                mma_f16(accH[2 * p],     aH, bb[0], bb[1]);
                mma_f16(accH[2 * p + 1], aH, bb[2], bb[3]);
            }
        }
    }

    float* o0 = outp + (m0 + rb) * OUTF + n0 + nw * 64;
    float* o1 = o0 + (size_t)8 * OUTF;
    float* o2 = o0 + (size_t)16 * OUTF;
    float* o3 = o0 + (size_t)24 * OUTF;
#pragma unroll
    for (int nt = 0; nt < 8; nt++) {
        int c = nt * 8 + 2 * qc;
        *(float2*)(o0 + c) = make_float2(accL[nt][0], accL[nt][1]);
        *(float2*)(o1 + c) = make_float2(accL[nt][2], accL[nt][3]);
        *(float2*)(o2 + c) = make_float2(accH[nt][0], accH[nt][1]);
        *(float2*)(o3 + c) = make_float2(accH[nt][2], accH[nt][3]);
    }
}

// ---------------------------------------------------------------------------
extern "C" void kernel_launch(void* const* d_in, const int* in_sizes, int n_in,
                              void* d_out, int out_size)
{
    const float* q  = (const float*)d_in[0];
    const float* k  = (const float*)d_in[1];
    const float* v  = (const float*)d_in[2];
    const float* Wq = (const float*)d_in[3];
    const float* Wk = (const float*)d_in[4];
    const float* Wv = (const float*)d_in[5];
    const float* Wo = (const float*)d_in[6];
    float* outp = (float*)d_out;

    static bool attr_done = false;
    if (!attr_done) {
        cudaFuncSetAttribute(flash14_kernel,
                             cudaFuncAttributeMaxDynamicSharedMemorySize,
                             3 * 18432);
        cudaFuncSetAttribute(flash14_kernel,
                             cudaFuncAttributePreferredSharedMemoryCarveout,
                             100);
        cudaFuncSetAttribute(outproj10_kernel,
                             cudaFuncAttributeMaxDynamicSharedMemorySize,
                             2 * 36864);
        cudaFuncSetAttribute(outproj10_kernel,
                             cudaFuncAttributePreferredSharedMemoryCarveout,
                             100);
        attr_done = true;
    }

    wo2h_kernel<<<OUTF * OUTF / 512, 256>>>(Wo);
    projM_kernel<<<dim3(Ss / 64, Bb * 3, 2), 128>>>(q, k, v, Wq, Wk, Wv);
    flash14_kernel<<<dim3(Ss / 128, Hh, Bb), 128, 3 * 18432>>>();
    outproj10_kernel<<<dim3(OUTF / 128, (Bb * Ss) / 128), 256,
                       2 * 36864>>>(outp);
}

// round 16
// speedup vs baseline: 1.0347x; 1.0347x over previous
#include <cuda_runtime.h>
#include <cuda_fp16.h>
#include <cstdint>

#define Bb 4
#define Ss 2048
#define Hh 16
#define Dd 64
#define OUTF 1024

// Scratch as packed half2 words (static device arrays — no runtime allocation).
__device__ uint32_t g_K[(size_t)Bb * Hh * Ss * Dd / 2];
__device__ uint32_t g_V[(size_t)Bb * Hh * Ss * Dd / 2];
__device__ uint32_t g_X[(size_t)Bb * Ss * (Hh * Dd) / 2];
__device__ uint32_t g_Wo[(size_t)OUTF * OUTF / 2];

__device__ __forceinline__ uint32_t h2(float a, float b) {
    __half2 t = __floats2half2_rn(a, b);
    return *(uint32_t*)&t;
}
__device__ __forceinline__ __half2 u2h(uint32_t x) { return *(__half2*)&x; }

__device__ __forceinline__ uint32_t ex2h2(uint32_t x) {
    uint32_t y;
    asm("ex2.approx.f16x2 %0, %1;" : "=r"(y) : "r"(x));
    return y;
}

// D += A(16x16 f16 row) * B(16x8 f16 col), fp32 accum.
__device__ __forceinline__ void mma_f16(float* c, const uint32_t* a,
                                        uint32_t b0, uint32_t b1) {
    asm volatile(
        "mma.sync.aligned.m16n8k16.row.col.f32.f16.f16.f32 "
        "{%0,%1,%2,%3}, {%4,%5,%6,%7}, {%8,%9}, {%0,%1,%2,%3};\n"
        : "+f"(c[0]), "+f"(c[1]), "+f"(c[2]), "+f"(c[3])
        : "r"(a[0]), "r"(a[1]), "r"(a[2]), "r"(a[3]), "r"(b0), "r"(b1));
}

// D += A(16x16 f16 row) * B(16x8 f16 col), f16 accum (C = 2 x f16x2 regs).
__device__ __forceinline__ void mma_h16(uint32_t* c, const uint32_t* a,
                                        uint32_t b0, uint32_t b1) {
    asm volatile(
        "mma.sync.aligned.m16n8k16.row.col.f16.f16.f16.f16 "
        "{%0,%1}, {%2,%3,%4,%5}, {%6,%7}, {%0,%1};\n"
        : "+r"(c[0]), "+r"(c[1])
        : "r"(a[0]), "r"(a[1]), "r"(a[2]), "r"(a[3]), "r"(b0), "r"(b1));
}

__device__ __forceinline__ void ldsm4(uint32_t* r, uint32_t addr) {
    asm volatile(
        "ldmatrix.sync.aligned.m8n8.x4.shared.b16 {%0,%1,%2,%3}, [%4];"
        : "=r"(r[0]), "=r"(r[1]), "=r"(r[2]), "=r"(r[3]) : "r"(addr));
}
__device__ __forceinline__ void ldsm4t(uint32_t* r, uint32_t addr) {
    asm volatile(
        "ldmatrix.sync.aligned.m8n8.x4.trans.shared.b16 {%0,%1,%2,%3}, [%4];"
        : "=r"(r[0]), "=r"(r[1]), "=r"(r[2]), "=r"(r[3]) : "r"(addr));
}
__device__ __forceinline__ uint32_t sptr(const void* p) {
    return (uint32_t)__cvta_generic_to_shared(p);
}
__device__ __forceinline__ void cpa16(uint32_t dst, const void* src) {
    asm volatile("cp.async.cg.shared.global [%0], [%1], 16;"
                 :: "r"(dst), "l"(src));
}
__device__ __forceinline__ void cpa_commit() {
    asm volatile("cp.async.commit_group;");
}
__device__ __forceinline__ void cpa_wait0() {
    asm volatile("cp.async.wait_group 0;");
}
__device__ __forceinline__ void cpa_wait1() {
    asm volatile("cp.async.wait_group 1;");
}

extern __shared__ uint32_t dyn_smem[];

// ---------------------------------------------------------------------------
// Kernel 0: Wo fp32 -> fp16 (half2-packed), once per launch.
// ---------------------------------------------------------------------------
__global__ __launch_bounds__(256) void wo2h_kernel(const float* __restrict__ Wo)
{
    int idx = blockIdx.x * 256 + threadIdx.x;
    float2 t = *(const float2*)(Wo + (size_t)idx * 2);
    g_Wo[idx] = h2(t.x, t.y);
}

// ---------------------------------------------------------------------------
// Kernel 1: K/V projections only (Q is fused into flash). 8 heads per CTA.
// grid (S/64, B*2, 2), 128 threads.
// ---------------------------------------------------------------------------
__global__ __launch_bounds__(128) void projKV_kernel(
    const float* __restrict__ k, const float* __restrict__ v,
    const float* __restrict__ Wk, const float* __restrict__ Wv)
{
    __shared__ uint32_t xs[64 * 36];
    __shared__ uint32_t ws[2][64 * 36];

    const int tid = threadIdx.x;
    const int warp = tid >> 5, lane = tid & 31;
    const int qr = lane >> 2, qc = lane & 3;
    const int s0 = blockIdx.x * 64;
    const int b  = blockIdx.y & 3;
    const int which = blockIdx.y >> 2;   // 0: K, 1: V
    const int h0 = blockIdx.z * 8;

    const float* x = (which == 0) ? k : v;
    const float* W = (which == 0) ? Wk : Wv;
    uint32_t* outb = (which == 0) ? g_K : g_V;

    for (int i = 0; i < 8; i++) {
        int idx = tid + i * 128;
        int r = idx >> 4, c4 = (idx & 15) << 2;
        float4 t = *(const float4*)(x + ((size_t)(b * Ss + s0 + r)) * Dd + c4);
        *(uint2*)&xs[r * 36 + (c4 >> 1)] = make_uint2(h2(t.x, t.y), h2(t.z, t.w));
        float4 w = *(const float4*)(W + ((size_t)h0 * Dd + r) * Dd + c4);
        *(uint2*)&ws[0][r * 36 + (c4 >> 1)] =
            make_uint2(h2(w.x, w.y), h2(w.z, w.w));
    }
    __syncthreads();

    const int g = lane >> 3, lr = lane & 7;
    const uint32_t afb = sptr(xs) +
        (uint32_t)(((warp * 16 + (g & 1) * 8 + lr) * 36 + (g >> 1) * 4) * 4);
    uint32_t a[4][4];
#pragma unroll
    for (int kt = 0; kt < 4; kt++) ldsm4(a[kt], afb + kt * 32);

    const uint32_t bfb0 = sptr(ws) +
        (uint32_t)((((g >> 1) * 8 + lr) * 36 + (g & 1) * 4) * 4);
    const int rlo = warp * 16 + qr;

    for (int hh = 0; hh < 8; hh++) {
        const int h = h0 + hh;
        float4 wreg[8];
        if (hh + 1 < 8) {
            const float* Wn = W + (size_t)(h + 1) * Dd * Dd;
#pragma unroll
            for (int i = 0; i < 8; i++) {
                int idx = tid + i * 128;
                int r = idx >> 4, c4 = (idx & 15) << 2;
                wreg[i] = *(const float4*)(Wn + (size_t)r * Dd + c4);
            }
        }

        const uint32_t bfb = bfb0 + (uint32_t)(hh & 1) * (64 * 36 * 4);
        float acc[8][4] = {};
#pragma unroll
        for (int kt = 0; kt < 4; kt++) {
#pragma unroll
            for (int p = 0; p < 4; p++) {
                uint32_t bb[4];
                ldsm4(bb, bfb + (uint32_t)(p * 2304 + kt * 32));
                mma_f16(acc[2 * p],     a[kt], bb[0], bb[1]);
                mma_f16(acc[2 * p + 1], a[kt], bb[2], bb[3]);
            }
        }

        uint32_t* o0 = outb + ((size_t)(b * Hh + h)) * Ss * 32
                       + (size_t)(s0 + rlo) * 32;
        uint32_t* o1 = o0 + 8 * 32;
#pragma unroll
        for (int nt = 0; nt < 8; nt++) {
            o0[nt * 4 + qc] = h2(acc[nt][0], acc[nt][1]);
            o1[nt * 4 + qc] = h2(acc[nt][2], acc[nt][3]);
        }

        if (hh + 1 < 8) {
#pragma unroll
            for (int i = 0; i < 8; i++) {
                int idx = tid + i * 128;
                int r = idx >> 4, c4 = (idx & 15) << 2;
                *(uint2*)&ws[(hh + 1) & 1][r * 36 + (c4 >> 1)] =
                    make_uint2(h2(wreg[i].x, wreg[i].y),
                               h2(wreg[i].z, wreg[i].w));
            }
        }
        __syncthreads();
    }
}

// ---------------------------------------------------------------------------
// Kernel 2: flash attention with FUSED Q projection. BM=128, BN=64, D=64,
// 128 threads, 32 Q-rows/warp, f16-accum QK^T, hadd softmax (R13), 3-stage
// cp.async KV ring + 9KB Wq staging region. qa fragments are computed
// in-prologue: Q = x_q @ (Wq * 0.125*log2e)^T on the tensor core.
// Dynamic smem: 3*18432 + 9216 = 64512 B.
// ---------------------------------------------------------------------------
__global__ __launch_bounds__(128, 3) void flash16_kernel(
    const float* __restrict__ qin, const float* __restrict__ Wq)
{
    const uint32_t sbase = sptr(dyn_smem);
    const uint32_t STG = 18432;
    const uint32_t WQOFF = 3 * STG;       // Wq staging region (bytes)

    const int tid = threadIdx.x;
    const int warp = tid >> 5, lane = tid & 31;
    const int qr = lane >> 2, qc = lane & 3;
    const int s0 = blockIdx.x * 128;
    const int h  = blockIdx.y;
    const int b  = blockIdx.z;
    const size_t base = ((size_t)(b * Hh + h)) * Ss * 32;
    const uint4* Ku4 = (const uint4*)(g_K + base);
    const uint4* Vu4 = (const uint4*)(g_V + base);
    const int rb = warp * 32 + qr;

    const int sr = tid >> 3;
    const int sc = tid & 7;
    uint32_t koff[4];
#pragma unroll
    for (int i = 0; i < 4; i++)
        koff[i] = (uint32_t)(((sr + 16 * i) * 36 + sc * 4) * 4);

    // Issue KV tiles 0,1 first so they land during the Q-proj prologue.
#pragma unroll
    for (int t = 0; t < 2; t++) {
        const uint4* Kn = Ku4 + (size_t)t * 512;
        const uint4* Vn = Vu4 + (size_t)t * 512;
        const uint32_t so = sbase + (uint32_t)t * STG;
#pragma unroll
        for (int i = 0; i < 4; i++) {
            cpa16(so + koff[i], Kn + (sr + 16 * i) * 8 + sc);
            cpa16(so + 9216 + koff[i], Vn + (sr + 16 * i) * 8 + sc);
        }
        cpa_commit();
    }

    // ---- Fused Q projection prologue ----
    // Stage Wq[h] * qs as f16 into smem [e][d/2], LD 36 words.
    {
        const float qs = 0.1803368801f;   // 0.125 * log2(e)
        const float* Wh = Wq + (size_t)h * Dd * Dd;
        uint32_t* wq = dyn_smem + (WQOFF >> 2);
#pragma unroll
        for (int i = 0; i < 8; i++) {
            int idx = tid + i * 128;
            int r = idx >> 4, c4 = (idx & 15) << 2;
            float4 w = *(const float4*)(Wh + (size_t)r * Dd + c4);
            *(uint2*)&wq[r * 36 + (c4 >> 1)] =
                make_uint2(h2(w.x * qs, w.y * qs), h2(w.z * qs, w.w * qs));
        }
    }

    // x_q A-fragments from fp32 gmem (warp rows rb.. via L/H halves).
    uint32_t xaL[4][4], xaH[4][4];
    {
        const float* x0 = qin + (size_t)(b * Ss + s0 + rb) * Dd;
        const float* x1 = x0 + 8 * Dd;
        const float* x2 = x0 + 16 * Dd;
        const float* x3 = x0 + 24 * Dd;
#pragma unroll
        for (int kt = 0; kt < 4; kt++) {
            int c = 16 * kt + 2 * qc;
            float2 t0 = *(const float2*)(x0 + c);
            float2 t1 = *(const float2*)(x1 + c);
            float2 t2 = *(const float2*)(x0 + c + 8);
            float2 t3 = *(const float2*)(x1 + c + 8);
            xaL[kt][0] = h2(t0.x, t0.y);
            xaL[kt][1] = h2(t1.x, t1.y);
            xaL[kt][2] = h2(t2.x, t2.y);
            xaL[kt][3] = h2(t3.x, t3.y);
            t0 = *(const float2*)(x2 + c);
            t1 = *(const float2*)(x3 + c);
            t2 = *(const float2*)(x2 + c + 8);
            t3 = *(const float2*)(x3 + c + 8);
            xaH[kt][0] = h2(t0.x, t0.y);
            xaH[kt][1] = h2(t1.x, t1.y);
            xaH[kt][2] = h2(t2.x, t2.y);
            xaH[kt][3] = h2(t3.x, t3.y);
        }
    }
    __syncthreads();   // Wq staged

    const int g = lane >> 3, lr = lane & 7;

    // Q = x @ Wq^T on the tensor core; repack C-frags into qa A-frags.
    uint32_t qaL[4][4], qaH[4][4];
    {
        const uint32_t wqb = sbase + WQOFF +
            (uint32_t)((((g >> 1) * 8 + lr) * 36 + (g & 1) * 4) * 4);
        float fL[8][4] = {}, fH[8][4] = {};
#pragma unroll
        for (int kt = 0; kt < 4; kt++) {
#pragma unroll
            for (int p = 0; p < 4; p++) {
                uint32_t wb[4];
                ldsm4(wb, wqb + (uint32_t)(p * 2304 + kt * 32));
                mma_f16(fL[2 * p],     xaL[kt], wb[0], wb[1]);
                mma_f16(fL[2 * p + 1], xaL[kt], wb[2], wb[3]);
                mma_f16(fH[2 * p],     xaH[kt], wb[0], wb[1]);
                mma_f16(fH[2 * p + 1], xaH[kt], wb[2], wb[3]);
            }
        }
#pragma unroll
        for (int kt = 0; kt < 4; kt++) {
            qaL[kt][0] = h2(fL[2 * kt][0],     fL[2 * kt][1]);
            qaL[kt][1] = h2(fL[2 * kt][2],     fL[2 * kt][3]);
            qaL[kt][2] = h2(fL[2 * kt + 1][0], fL[2 * kt + 1][1]);
            qaL[kt][3] = h2(fL[2 * kt + 1][2], fL[2 * kt + 1][3]);
            qaH[kt][0] = h2(fH[2 * kt][0],     fH[2 * kt][1]);
            qaH[kt][1] = h2(fH[2 * kt][2],     fH[2 * kt][3]);
            qaH[kt][2] = h2(fH[2 * kt + 1][0], fH[2 * kt + 1][1]);
            qaH[kt][3] = h2(fH[2 * kt + 1][2], fH[2 * kt + 1][3]);
        }
    }

    const uint32_t kfb = sbase +
        (uint32_t)((((g >> 1) * 8 + lr) * 36 + (g & 1) * 4) * 4);
    const uint32_t vfb = sbase + 9216 +
        (uint32_t)(((((g & 1) * 8) + lr) * 36 + (lane >> 4) * 4) * 4);

    float oaccL[8][4] = {}, oaccH[8][4] = {};
    float l0 = 0.f, l1 = 0.f, l2 = 0.f, l3 = 0.f;
    int stage = 0;

    for (int jt = 0; jt < Ss / 64; jt++) {
        cpa_wait1();
        __syncthreads();

        if (jt + 2 < Ss / 64) {
            int s2 = stage + 2; if (s2 >= 3) s2 -= 3;
            const uint32_t fo = sbase + (uint32_t)s2 * STG;
            const uint4* Kn = Ku4 + (size_t)(jt + 2) * 512;
            const uint4* Vn = Vu4 + (size_t)(jt + 2) * 512;
#pragma unroll
            for (int i = 0; i < 4; i++) {
                cpa16(fo + koff[i], Kn + (sr + 16 * i) * 8 + sc);
                cpa16(fo + 9216 + koff[i], Vn + (sr + 16 * i) * 8 + sc);
            }
        }
        cpa_commit();

        const uint32_t so = (uint32_t)stage * STG;

        // S = Q K^T, f16 accumulation.
        uint32_t sL[8][2], sH[8][2];
#pragma unroll
        for (int nt = 0; nt < 8; nt++) {
            sL[nt][0] = 0u; sL[nt][1] = 0u;
            sH[nt][0] = 0u; sH[nt][1] = 0u;
        }
#pragma unroll
        for (int kt = 0; kt < 4; kt++) {
#pragma unroll
            for (int p = 0; p < 4; p++) {
                uint32_t kb[4];
                ldsm4(kb, kfb + so + (uint32_t)(p * 2304 + kt * 32));
                mma_h16(sL[2 * p],     qaL[kt], kb[0], kb[1]);
                mma_h16(sL[2 * p + 1], qaL[kt], kb[2], kb[3]);
                mma_h16(sH[2 * p],     qaH[kt], kb[0], kb[1]);
                mma_h16(sH[2 * p + 1], qaH[kt], kb[2], kb[3]);
            }
        }

        // P = exp2(S) directly on f16x2 C-fragments.
        uint32_t peL0[8], peL1[8], peH0[8], peH1[8];
#pragma unroll
        for (int nt = 0; nt < 8; nt++) {
            peL0[nt] = ex2h2(sL[nt][0]);
            peL1[nt] = ex2h2(sL[nt][1]);
            peH0[nt] = ex2h2(sH[nt][0]);
            peH1[nt] = ex2h2(sH[nt][1]);
        }
        {
            __half2 a0 = __hadd2(__hadd2(u2h(peL0[0]), u2h(peL0[1])),
                                 __hadd2(u2h(peL0[2]), u2h(peL0[3])));
            __half2 a1 = __hadd2(__hadd2(u2h(peL0[4]), u2h(peL0[5])),
                                 __hadd2(u2h(peL0[6]), u2h(peL0[7])));
            __half2 b0 = __hadd2(__hadd2(u2h(peL1[0]), u2h(peL1[1])),
                                 __hadd2(u2h(peL1[2]), u2h(peL1[3])));
            __half2 b1 = __hadd2(__hadd2(u2h(peL1[4]), u2h(peL1[5])),
                                 __hadd2(u2h(peL1[6]), u2h(peL1[7])));
            __half2 c0 = __hadd2(__hadd2(u2h(peH0[0]), u2h(peH0[1])),
                                 __hadd2(u2h(peH0[2]), u2h(peH0[3])));
            __half2 c1 = __hadd2(__hadd2(u2h(peH0[4]), u2h(peH0[5])),
                                 __hadd2(u2h(peH0[6]), u2h(peH0[7])));
            __half2 d0 = __hadd2(__hadd2(u2h(peH1[0]), u2h(peH1[1])),
                                 __hadd2(u2h(peH1[2]), u2h(peH1[3])));
            __half2 d1 = __hadd2(__hadd2(u2h(peH1[4]), u2h(peH1[5])),
                                 __hadd2(u2h(peH1[6]), u2h(peH1[7])));
            float2 f0 = __half22float2(a0), f1 = __half22float2(a1);
            float rs0 = (f0.x + f0.y) + (f1.x + f1.y);
            f0 = __half22float2(b0); f1 = __half22float2(b1);
            float rs1 = (f0.x + f0.y) + (f1.x + f1.y);
            f0 = __half22float2(c0); f1 = __half22float2(c1);
            float rs2 = (f0.x + f0.y) + (f1.x + f1.y);
            f0 = __half22float2(d0); f1 = __half22float2(d1);
            float rs3 = (f0.x + f0.y) + (f1.x + f1.y);
            rs0 += __shfl_xor_sync(0xffffffffu, rs0, 1);
            rs0 += __shfl_xor_sync(0xffffffffu, rs0, 2);
            rs1 += __shfl_xor_sync(0xffffffffu, rs1, 1);
            rs1 += __shfl_xor_sync(0xffffffffu, rs1, 2);
            rs2 += __shfl_xor_sync(0xffffffffu, rs2, 1);
            rs2 += __shfl_xor_sync(0xffffffffu, rs2, 2);
            rs3 += __shfl_xor_sync(0xffffffffu, rs3, 1);
            rs3 += __shfl_xor_sync(0xffffffffu, rs3, 2);
            l0 += rs0; l1 += rs1; l2 += rs2; l3 += rs3;
        }

        // O += P V (fp32 accum).
#pragma unroll
        for (int kt = 0; kt < 4; kt++) {
            uint32_t paL[4] = { peL0[2 * kt], peL1[2 * kt],
                                peL0[2 * kt + 1], peL1[2 * kt + 1] };
            uint32_t paH[4] = { peH0[2 * kt], peH1[2 * kt],
                                peH0[2 * kt + 1], peH1[2 * kt + 1] };
#pragma unroll
            for (int e0 = 0; e0 < 8; e0 += 2) {
                uint32_t vb[4];
                ldsm4t(vb, vfb + so + (uint32_t)(kt * 2304 + e0 * 16));
                mma_f16(oaccL[e0],     paL, vb[0], vb[1]);
                mma_f16(oaccL[e0 + 1], paL, vb[2], vb[3]);
                mma_f16(oaccH[e0],     paH, vb[0], vb[1]);
                mma_f16(oaccH[e0 + 1], paH, vb[2], vb[3]);
            }
        }

        if (++stage == 3) stage = 0;
    }

    float inv0 = 1.0f / l0, inv1 = 1.0f / l1;
    float inv2 = 1.0f / l2, inv3 = 1.0f / l3;
    uint32_t* x0 = g_X + (size_t)(b * Ss + s0 + rb) * 512 + h * 32;
    uint32_t* x1 = x0 + (size_t)8 * 512;
    uint32_t* x2 = x0 + (size_t)16 * 512;
    uint32_t* x3 = x0 + (size_t)24 * 512;
#pragma unroll
    for (int et = 0; et < 8; et++) {
        x0[et * 4 + qc] = h2(oaccL[et][0] * inv0, oaccL[et][1] * inv0);
        x1[et * 4 + qc] = h2(oaccL[et][2] * inv1, oaccL[et][3] * inv1);
        x2[et * 4 + qc] = h2(oaccH[et][0] * inv2, oaccH[et][1] * inv2);
        x3[et * 4 + qc] = h2(oaccH[et][2] * inv3, oaccH[et][3] * inv3);
    }
}

// ---------------------------------------------------------------------------
// Kernel 3: output projection (R10 version, unchanged).
// ---------------------------------------------------------------------------
__global__ __launch_bounds__(256, 2) void outproj10_kernel(float* __restrict__ outp)
{
    const uint32_t sbase = sptr(dyn_smem);
    const uint32_t STG = 36864;

    const int tid = threadIdx.x;
    const int warp = tid >> 5, lane = tid & 31;
    const int qr = lane >> 2, qc = lane & 3;
    const int mw = warp >> 1;
    const int nw = warp & 1;
    const int n0 = blockIdx.x * 128;
    const size_t m0 = (size_t)blockIdx.y * 128;
    const int rb = mw * 32 + qr;

    const uint4* Xu4 = (const uint4*)g_X;
    const uint4* Wu4 = (const uint4*)g_Wo;

    const int cr = tid >> 3;
    const int cc = tid & 7;
    uint32_t roff[4];
#pragma unroll
    for (int i = 0; i < 4; i++)
        roff[i] = (uint32_t)(((cr + 32 * i) * 36 + cc * 4) * 4);

#pragma unroll
    for (int i = 0; i < 4; i++) {
        int r = cr + 32 * i;
        cpa16(sbase + roff[i], Xu4 + (m0 + r) * 128 + cc);
        cpa16(sbase + 18432 + roff[i], Wu4 + (size_t)(n0 + r) * 128 + cc);
    }
    cpa_commit();

    const int g = lane >> 3, lr = lane & 7;
    const uint32_t afbL = sbase +
        (uint32_t)(((mw * 32 + (g & 1) * 8 + lr) * 36 + (g >> 1) * 4) * 4);
    const uint32_t afbH = afbL + 16 * 36 * 4;
    const uint32_t bfb = sbase + 18432 +
        (uint32_t)(((nw * 64 + (g >> 1) * 8 + lr) * 36 + (g & 1) * 4) * 4);

    float accL[8][4] = {}, accH[8][4] = {};

    for (int kc = 0; kc < 16; kc++) {
        cpa_wait0();
        __syncthreads();

        if (kc + 1 < 16) {
            const uint32_t fo = sbase + (uint32_t)((kc + 1) & 1) * STG;
            const int k4 = (kc + 1) * 8;
#pragma unroll
            for (int i = 0; i < 4; i++) {
                int r = cr + 32 * i;
                cpa16(fo + roff[i], Xu4 + (m0 + r) * 128 + k4 + cc);
                cpa16(fo + 18432 + roff[i],
                      Wu4 + (size_t)(n0 + r) * 128 + k4 + cc);
            }
            cpa_commit();
        }

        const uint32_t so = (uint32_t)(kc & 1) * STG;
#pragma unroll
        for (int kt = 0; kt < 4; kt++) {
            uint32_t aL[4], aH[4];
            ldsm4(aL, afbL + so + (uint32_t)(kt * 32));
            ldsm4(aH, afbH + so + (uint32_t)(kt * 32));
#pragma unroll
            for (int p = 0; p < 4; p++) {
                uint32_t bb[4];
                ldsm4(bb, bfb + so + (uint32_t)(p * 2304 + kt * 32));
                mma_f16(accL[2 * p],     aL, bb[0], bb[1]);
                mma_f16(accL[2 * p + 1], aL, bb[2], bb[3]);
                mma_f16(accH[2 * p],     aH, bb[0], bb[1]);
                mma_f16(accH[2 * p + 1], aH, bb[2], bb[3]);
            }
        }
    }

    float* o0 = outp + (m0 + rb) * OUTF + n0 + nw * 64;
    float* o1 = o0 + (size_t)8 * OUTF;
    float* o2 = o0 + (size_t)16 * OUTF;
    float* o3 = o0 + (size_t)24 * OUTF;
#pragma unroll
    for (int nt = 0; nt < 8; nt++) {
        int c = nt * 8 + 2 * qc;
        *(float2*)(o0 + c) = make_float2(accL[nt][0], accL[nt][1]);
        *(float2*)(o1 + c) = make_float2(accL[nt][2], accL[nt][3]);
        *(float2*)(o2 + c) = make_float2(accH[nt][0], accH[nt][1]);
        *(float2*)(o3 + c) = make_float2(accH[nt][2], accH[nt][3]);
    }
}

// ---------------------------------------------------------------------------
extern "C" void kernel_launch(void* const* d_in, const int* in_sizes, int n_in,
                              void* d_out, int out_size)
{
    const float* q  = (const float*)d_in[0];
    const float* k  = (const float*)d_in[1];
    const float* v  = (const float*)d_in[2];
    const float* Wq = (const float*)d_in[3];
    const float* Wk = (const float*)d_in[4];
    const float* Wv = (const float*)d_in[5];
    const float* Wo = (const float*)d_in[6];
    float* outp = (float*)d_out;

    static bool attr_done = false;
    if (!attr_done) {
        cudaFuncSetAttribute(flash16_kernel,
                             cudaFuncAttributeMaxDynamicSharedMemorySize,
                             3 * 18432 + 9216);
        cudaFuncSetAttribute(flash16_kernel,
                             cudaFuncAttributePreferredSharedMemoryCarveout,
                             100);
        cudaFuncSetAttribute(outproj10_kernel,
                             cudaFuncAttributeMaxDynamicSharedMemorySize,
                             2 * 36864);
        cudaFuncSetAttribute(outproj10_kernel,
                             cudaFuncAttributePreferredSharedMemoryCarveout,
                             100);
        attr_done = true;
    }

    wo2h_kernel<<<OUTF * OUTF / 512, 256>>>(Wo);
    projKV_kernel<<<dim3(Ss / 64, Bb * 2, 2), 128>>>(k, v, Wk, Wv);
    flash16_kernel<<<dim3(Ss / 128, Hh, Bb), 128, 3 * 18432 + 9216>>>(q, Wq);
    outproj10_kernel<<<dim3(OUTF / 128, (Bb * Ss) / 128), 256,
                       2 * 36864>>>(outp);
}